// round 4
// baseline (speedup 1.0000x reference)
#include <cuda_runtime.h>
#include <cuda_fp16.h>
#include <cstdint>

// Problem dims
#define T_DIM 8192
#define K_DIM 4096
#define O_DIM 11008
#define QB    64

// int8 correction GEMM: K = 8192 (xl*wh | xh*wl concatenated)
#define K8 8192

// GEMM tiling (both GEMMs): 128 x 256 CTA tile, 128-byte K-slab per stage
#define BM 128
#define BN 256
#define NSTAGE 3
#define NTHREADS 512
#define KBLK16 (K_DIM / 64)   // 64 fp16 k-blocks (64 halfs = 128 B)
#define KBLK8  (K8 / 128)     // 64 int8 k-blocks (128 bytes)

#define A_ST_BYTES (BM * 128)
#define B_ST_BYTES (BN * 128)
#define STAGE_BYTES (A_ST_BYTES + B_ST_BYTES)   // 49152
#define SMEM_TOTAL (NSTAGE * STAGE_BYTES)        // 147456

// Scratch (static device arrays: allocation-free contract)
__device__ __align__(16) __half g_xh[(size_t)T_DIM * K_DIM];   // fp16(x)
__device__ __align__(16) __half g_wh[(size_t)O_DIM * K_DIM];   // fp16(w*s)
__device__ __align__(16) int8_t g_a8[(size_t)T_DIM * K8];      // [xl8 | xh8]
__device__ __align__(16) int8_t g_b8[(size_t)O_DIM * K8];      // [wh8 | wl8]
__device__ float g_sxh[T_DIM];
__device__ float g_swh[O_DIM];

// ---------------------------------------------------------------- helpers
__device__ __forceinline__ uint32_t smem_u32(const void* p) {
    uint32_t a;
    asm("{ .reg .u64 t; cvta.to.shared.u64 t, %1; cvt.u32.u64 %0, t; }" : "=r"(a) : "l"(p));
    return a;
}
__device__ __forceinline__ uint32_t swz(uint32_t off) { return off ^ ((off >> 3) & 0x70); }

__device__ __forceinline__ void cp_async16(uint32_t dst, const void* src) {
    asm volatile("cp.async.cg.shared.global [%0], [%1], 16;\n" :: "r"(dst), "l"(src));
}
__device__ __forceinline__ void cp_commit() { asm volatile("cp.async.commit_group;\n" ::: "memory"); }
template <int N>
__device__ __forceinline__ void cp_wait() { asm volatile("cp.async.wait_group %0;\n" :: "n"(N) : "memory"); }

#define LDSM_X4(r, addr) \
    asm volatile("ldmatrix.sync.aligned.m8n8.x4.shared.b16 {%0,%1,%2,%3}, [%4];" \
        : "=r"((r)[0]), "=r"((r)[1]), "=r"((r)[2]), "=r"((r)[3]) : "r"(addr))

#define MMA16816(c, a, b0, b1) \
    asm volatile("mma.sync.aligned.m16n8k16.row.col.f32.f16.f16.f32 " \
        "{%0,%1,%2,%3}, {%4,%5,%6,%7}, {%8,%9}, {%0,%1,%2,%3};" \
        : "+f"((c)[0]), "+f"((c)[1]), "+f"((c)[2]), "+f"((c)[3]) \
        : "r"((a)[0]), "r"((a)[1]), "r"((a)[2]), "r"((a)[3]), "r"(b0), "r"(b1))

#define MMA16832I(c, a, b0, b1) \
    asm volatile("mma.sync.aligned.m16n8k32.row.col.s32.s8.s8.s32 " \
        "{%0,%1,%2,%3}, {%4,%5,%6,%7}, {%8,%9}, {%0,%1,%2,%3};" \
        : "+r"((c)[0]), "+r"((c)[1]), "+r"((c)[2]), "+r"((c)[3]) \
        : "r"((a)[0]), "r"((a)[1]), "r"((a)[2]), "r"((a)[3]), "r"(b0), "r"(b1))

__device__ __forceinline__ int q8(float v) {
    int q = __float2int_rn(v);
    return min(max(q, -127), 127);
}
__device__ __forceinline__ uint32_t pack4(int a, int b, int c, int d) {
    return (uint32_t)(a & 0xFF) | ((uint32_t)(b & 0xFF) << 8) |
           ((uint32_t)(c & 0xFF) << 16) | ((uint32_t)(d & 0xFF) << 24);
}

// ---------------------------------------------------------------- row-max kernels
__global__ void __launch_bounds__(256) rowmax_x(const float* __restrict__ x) {
    const int row = blockIdx.x;
    const float4* xr = reinterpret_cast<const float4*>(x + (size_t)row * K_DIM);
    float m = 0.f;
    for (int i = threadIdx.x; i < K_DIM / 4; i += 256) {
        float4 f = xr[i];
        m = fmaxf(m, fmaxf(fmaxf(fabsf(f.x), fabsf(f.y)), fmaxf(fabsf(f.z), fabsf(f.w))));
    }
    #pragma unroll
    for (int o = 16; o; o >>= 1) m = fmaxf(m, __shfl_xor_sync(~0u, m, o));
    __shared__ float sm[8];
    if ((threadIdx.x & 31) == 0) sm[threadIdx.x >> 5] = m;
    __syncthreads();
    if (threadIdx.x < 8) {
        float v = sm[threadIdx.x];
        #pragma unroll
        for (int o = 4; o; o >>= 1) v = fmaxf(v, __shfl_xor_sync(0xFFu, v, o));
        if (threadIdx.x == 0) g_sxh[row] = fmaxf(v, 1e-30f) * (1.f / 127.f);
    }
}

__global__ void __launch_bounds__(256) rowmax_w(const float* __restrict__ w,
                                                const float* __restrict__ s) {
    const int row = blockIdx.x;
    const float4* wr = reinterpret_cast<const float4*>(w + (size_t)row * K_DIM);
    const float* srow = s + (size_t)(row >> 6) * (K_DIM / QB);
    float m = 0.f;
    for (int i = threadIdx.x; i < K_DIM / 4; i += 256) {
        float sc = srow[(i * 4) >> 6];
        float4 f = wr[i];
        m = fmaxf(m, fmaxf(fmaxf(fabsf(f.x), fabsf(f.y)), fmaxf(fabsf(f.z), fabsf(f.w))) * sc);
    }
    #pragma unroll
    for (int o = 16; o; o >>= 1) m = fmaxf(m, __shfl_xor_sync(~0u, m, o));
    __shared__ float sm[8];
    if ((threadIdx.x & 31) == 0) sm[threadIdx.x >> 5] = m;
    __syncthreads();
    if (threadIdx.x < 8) {
        float v = sm[threadIdx.x];
        #pragma unroll
        for (int o = 4; o; o >>= 1) v = fmaxf(v, __shfl_xor_sync(0xFFu, v, o));
        if (threadIdx.x == 0) g_swh[row] = fmaxf(v, 1e-30f) * (1.f / 127.f);
    }
}

// ---------------------------------------------------------------- split/quant prep
__global__ void __launch_bounds__(256) xprep(const float* __restrict__ x) {
    const size_t n4 = (size_t)T_DIM * K_DIM / 4;
    for (size_t v = (size_t)blockIdx.x * blockDim.x + threadIdx.x; v < n4;
         v += (size_t)gridDim.x * blockDim.x) {
        size_t e = v * 4;
        size_t t = e >> 12;           // /4096
        size_t i = e & 4095;
        const float inv = 1.f / g_sxh[t];
        float4 f = reinterpret_cast<const float4*>(x)[v];
        __half h0 = __float2half_rn(f.x), h1 = __float2half_rn(f.y);
        __half h2 = __float2half_rn(f.z), h3 = __float2half_rn(f.w);
        float l0 = f.x - __half2float(h0), l1 = f.y - __half2float(h1);
        float l2 = f.z - __half2float(h2), l3 = f.w - __half2float(h3);
        __half2 p0 = __halves2half2(h0, h1), p1 = __halves2half2(h2, h3);
        uint2 uh;
        uh.x = *reinterpret_cast<uint32_t*>(&p0);
        uh.y = *reinterpret_cast<uint32_t*>(&p1);
        *reinterpret_cast<uint2*>(g_xh + t * K_DIM + i) = uh;
        uint32_t ph = pack4(q8(f.x * inv), q8(f.y * inv), q8(f.z * inv), q8(f.w * inv));
        const float invl = inv * 2048.f;
        uint32_t pl = pack4(q8(l0 * invl), q8(l1 * invl), q8(l2 * invl), q8(l3 * invl));
        *reinterpret_cast<uint32_t*>(g_a8 + t * K8 + i) = pl;            // xl8
        *reinterpret_cast<uint32_t*>(g_a8 + t * K8 + K_DIM + i) = ph;    // xh8
    }
}

__global__ void __launch_bounds__(256) wprep(const float* __restrict__ w,
                                             const float* __restrict__ s) {
    const size_t n4 = (size_t)O_DIM * K_DIM / 4;
    for (size_t v = (size_t)blockIdx.x * blockDim.x + threadIdx.x; v < n4;
         v += (size_t)gridDim.x * blockDim.x) {
        size_t e = v * 4;
        size_t o = e >> 12;
        size_t i = e & 4095;
        float sc = s[(o >> 6) * (K_DIM / QB) + (i >> 6)];
        const float inv = 1.f / g_swh[o];
        float4 f = reinterpret_cast<const float4*>(w)[v];
        float d0 = f.x * sc, d1 = f.y * sc, d2 = f.z * sc, d3 = f.w * sc;
        __half h0 = __float2half_rn(d0), h1 = __float2half_rn(d1);
        __half h2 = __float2half_rn(d2), h3 = __float2half_rn(d3);
        float l0 = d0 - __half2float(h0), l1 = d1 - __half2float(h1);
        float l2 = d2 - __half2float(h2), l3 = d3 - __half2float(h3);
        __half2 p0 = __halves2half2(h0, h1), p1 = __halves2half2(h2, h3);
        uint2 uh;
        uh.x = *reinterpret_cast<uint32_t*>(&p0);
        uh.y = *reinterpret_cast<uint32_t*>(&p1);
        *reinterpret_cast<uint2*>(g_wh + o * K_DIM + i) = uh;
        uint32_t ph = pack4(q8(d0 * inv), q8(d1 * inv), q8(d2 * inv), q8(d3 * inv));
        const float invl = inv * 2048.f;
        uint32_t pl = pack4(q8(l0 * invl), q8(l1 * invl), q8(l2 * invl), q8(l3 * invl));
        *reinterpret_cast<uint32_t*>(g_b8 + o * K8 + i) = ph;            // wh8
        *reinterpret_cast<uint32_t*>(g_b8 + o * K8 + K_DIM + i) = pl;    // wl8
    }
}

// ---------------------------------------------------------------- int8 correction GEMM
// out[r][c] = (float)acc_s32 * sxh[r]*swh[c]/2048   (written first; fp16 GEMM accumulates)
__global__ void __launch_bounds__(NTHREADS, 1) gemm_i8(float* __restrict__ out) {
    extern __shared__ char smem[];
    const uint32_t sbase = smem_u32(smem);
    const int tid = threadIdx.x;
    const int wid = tid >> 5;
    const int lid = tid & 31;

    const int t0 = blockIdx.x * BM;
    const int o0 = blockIdx.y * BN;

    const int8_t* Ag = g_a8 + (size_t)t0 * K8;
    const int8_t* Bg = g_b8 + (size_t)o0 * K8;

    auto load_stage = [&](int st, int kb) {
        if (kb < KBLK8) {
            const uint32_t abase = sbase + st * STAGE_BYTES;
            const uint32_t bbase = abase + A_ST_BYTES;
            const int kk = kb * 128;
            #pragma unroll
            for (int c = tid; c < (BM + BN) * 8; c += NTHREADS) {
                int row = c >> 3, ch = c & 7;
                if (row < BM)
                    cp_async16(abase + swz(row * 128 + ch * 16),
                               Ag + (size_t)row * K8 + kk + ch * 16);
                else
                    cp_async16(bbase + swz((row - BM) * 128 + ch * 16),
                               Bg + (size_t)(row - BM) * K8 + kk + ch * 16);
            }
        }
        cp_commit();
    };

    const int warp_m = wid & 1;
    const int warp_n = wid >> 1;
    const int m_off = warp_m * 64;
    const int n_off = warp_n * 32;
    const int lrow = lid & 15;
    const int lc16 = lid >> 4;

    uint32_t preA[4], preB[2];
    #pragma unroll
    for (int mi = 0; mi < 4; mi++)
        preA[mi] = swz((uint32_t)((m_off + mi * 16 + lrow) * 128 + lc16 * 16));
    #pragma unroll
    for (int nj = 0; nj < 2; nj++)
        preB[nj] = swz((uint32_t)((n_off + nj * 16 + lrow) * 128 + lc16 * 16));

    int acc[4][4][4];
    #pragma unroll
    for (int mi = 0; mi < 4; mi++)
        #pragma unroll
        for (int ni = 0; ni < 4; ni++)
            #pragma unroll
            for (int q = 0; q < 4; q++) acc[mi][ni][q] = 0;

    load_stage(0, 0);
    load_stage(1, 1);

    for (int kb = 0; kb < KBLK8; kb++) {
        cp_wait<1>();
        __syncthreads();
        load_stage((kb + 2) % NSTAGE, kb + 2);

        const uint32_t sA = sbase + (kb % NSTAGE) * STAGE_BYTES;
        const uint32_t sB = sA + A_ST_BYTES;
        #pragma unroll
        for (int ks = 0; ks < 4; ks++) {   // 4 x k32 (32B) steps per 128B slab
            const uint32_t xk = ks * 32;
            uint32_t a[4][4], b[2][4];
            #pragma unroll
            for (int mi = 0; mi < 4; mi++) LDSM_X4(a[mi], sA + (preA[mi] ^ xk));
            #pragma unroll
            for (int nj = 0; nj < 2; nj++) LDSM_X4(b[nj], sB + (preB[nj] ^ xk));
            #pragma unroll
            for (int mi = 0; mi < 4; mi++)
                #pragma unroll
                for (int ni = 0; ni < 4; ni++)
                    MMA16832I(acc[mi][ni], a[mi], b[ni >> 1][ni & 1], b[ni >> 1][2 + (ni & 1)]);
        }
    }

    // Epilogue: scale and write
    #pragma unroll
    for (int mi = 0; mi < 4; mi++) {
        const int r0 = t0 + m_off + mi * 16 + (lid >> 2);
        const float sr0 = g_sxh[r0] * (1.f / 2048.f);
        const float sr1 = g_sxh[r0 + 8] * (1.f / 2048.f);
        #pragma unroll
        for (int ni = 0; ni < 4; ni++) {
            const int c = o0 + n_off + ni * 8 + ((lid & 3) << 1);
            const float sc0 = g_swh[c], sc1 = g_swh[c + 1];
            *reinterpret_cast<float2*>(out + (size_t)r0 * O_DIM + c) =
                make_float2((float)acc[mi][ni][0] * sr0 * sc0,
                            (float)acc[mi][ni][1] * sr0 * sc1);
            *reinterpret_cast<float2*>(out + (size_t)(r0 + 8) * O_DIM + c) =
                make_float2((float)acc[mi][ni][2] * sr1 * sc0,
                            (float)acc[mi][ni][3] * sr1 * sc1);
        }
    }
}

// ---------------------------------------------------------------- fp16 main GEMM (accumulates)
__global__ void __launch_bounds__(NTHREADS, 1) gemm_f16(float* __restrict__ out) {
    extern __shared__ char smem[];
    const uint32_t sbase = smem_u32(smem);
    const int tid = threadIdx.x;
    const int wid = tid >> 5;
    const int lid = tid & 31;

    const int t0 = blockIdx.x * BM;
    const int o0 = blockIdx.y * BN;

    const __half* Ag = g_xh + (size_t)t0 * K_DIM;
    const __half* Bg = g_wh + (size_t)o0 * K_DIM;

    auto load_stage = [&](int st, int kb) {
        if (kb < KBLK16) {
            const uint32_t abase = sbase + st * STAGE_BYTES;
            const uint32_t bbase = abase + A_ST_BYTES;
            const int kk = kb * 64;
            #pragma unroll
            for (int c = tid; c < (BM + BN) * 8; c += NTHREADS) {
                int row = c >> 3, ch = c & 7;
                if (row < BM)
                    cp_async16(abase + swz(row * 128 + ch * 16),
                               Ag + (size_t)row * K_DIM + kk + ch * 8);
                else
                    cp_async16(bbase + swz((row - BM) * 128 + ch * 16),
                               Bg + (size_t)(row - BM) * K_DIM + kk + ch * 8);
            }
        }
        cp_commit();
    };

    const int warp_m = wid & 1;
    const int warp_n = wid >> 1;
    const int m_off = warp_m * 64;
    const int n_off = warp_n * 32;
    const int lrow = lid & 15;
    const int lc16 = lid >> 4;

    uint32_t preA[4], preB[2];
    #pragma unroll
    for (int mi = 0; mi < 4; mi++)
        preA[mi] = swz((uint32_t)((m_off + mi * 16 + lrow) * 128 + lc16 * 16));
    #pragma unroll
    for (int nj = 0; nj < 2; nj++)
        preB[nj] = swz((uint32_t)((n_off + nj * 16 + lrow) * 128 + lc16 * 16));

    float acc[4][4][4];
    #pragma unroll
    for (int mi = 0; mi < 4; mi++)
        #pragma unroll
        for (int ni = 0; ni < 4; ni++)
            #pragma unroll
            for (int q = 0; q < 4; q++) acc[mi][ni][q] = 0.f;

    load_stage(0, 0);
    load_stage(1, 1);

    for (int kb = 0; kb < KBLK16; kb++) {
        cp_wait<1>();
        __syncthreads();
        load_stage((kb + 2) % NSTAGE, kb + 2);

        const uint32_t sA = sbase + (kb % NSTAGE) * STAGE_BYTES;
        const uint32_t sB = sA + A_ST_BYTES;
        #pragma unroll
        for (int ks = 0; ks < 4; ks++) {
            const uint32_t xk = ks * 32;
            uint32_t a[4][4], b[2][4];
            #pragma unroll
            for (int mi = 0; mi < 4; mi++) LDSM_X4(a[mi], sA + (preA[mi] ^ xk));
            #pragma unroll
            for (int nj = 0; nj < 2; nj++) LDSM_X4(b[nj], sB + (preB[nj] ^ xk));
            #pragma unroll
            for (int mi = 0; mi < 4; mi++)
                #pragma unroll
                for (int ni = 0; ni < 4; ni++)
                    MMA16816(acc[mi][ni], a[mi], b[ni >> 1][ni & 1], b[ni >> 1][2 + (ni & 1)]);
        }
    }

    // Epilogue: accumulate onto int8-correction result
    #pragma unroll
    for (int mi = 0; mi < 4; mi++) {
        const int r0 = t0 + m_off + mi * 16 + (lid >> 2);
        #pragma unroll
        for (int ni = 0; ni < 4; ni++) {
            const int c = o0 + n_off + ni * 8 + ((lid & 3) << 1);
            float2* p0 = reinterpret_cast<float2*>(out + (size_t)r0 * O_DIM + c);
            float2* p1 = reinterpret_cast<float2*>(out + (size_t)(r0 + 8) * O_DIM + c);
            float2 v0 = *p0, v1 = *p1;
            v0.x += acc[mi][ni][0]; v0.y += acc[mi][ni][1];
            v1.x += acc[mi][ni][2]; v1.y += acc[mi][ni][3];
            *p0 = v0; *p1 = v1;
        }
    }
}

// ---------------------------------------------------------------- launch
extern "C" void kernel_launch(void* const* d_in, const int* in_sizes, int n_in,
                              void* d_out, int out_size) {
    (void)in_sizes; (void)n_in; (void)out_size;
    const float* x = (const float*)d_in[0];
    const float* w = (const float*)d_in[1];
    const float* s = (const float*)d_in[2];
    float* out = (float*)d_out;

    rowmax_x<<<T_DIM, 256>>>(x);
    rowmax_w<<<O_DIM, 256>>>(w, s);
    xprep<<<2048, 256>>>(x);
    wprep<<<2048, 256>>>(w, s);

    cudaFuncSetAttribute(gemm_i8, cudaFuncAttributeMaxDynamicSharedMemorySize, SMEM_TOTAL);
    cudaFuncSetAttribute(gemm_f16, cudaFuncAttributeMaxDynamicSharedMemorySize, SMEM_TOTAL);
    dim3 grid(T_DIM / BM, O_DIM / BN);  // (64, 43)
    gemm_i8<<<grid, NTHREADS, SMEM_TOTAL>>>(out);   // writes out = correction
    gemm_f16<<<grid, NTHREADS, SMEM_TOTAL>>>(out);  // out += main product
}

// round 5
// speedup vs baseline: 1.8920x; 1.8920x over previous
#include <cuda_runtime.h>
#include <cuda_fp16.h>
#include <cstdint>

// Problem dims
#define T_DIM 8192
#define K_DIM 4096
#define O_DIM 11008
#define QB    64

// fp8 correction GEMM: K = 8192 (xl*wh | xh*wl concatenated)
#define K8 8192

// GEMM tiling (both GEMMs): 128 x 256 CTA tile, 128-byte K-slab per stage
#define BM 128
#define BN 256
#define NSTAGE 3
#define NTHREADS 512
#define KBLK16 (K_DIM / 64)   // 64 fp16 k-blocks (64 halfs = 128 B)
#define KBLK8  (K8 / 128)     // 64 fp8 k-blocks (128 bytes)

#define A_ST_BYTES (BM * 128)
#define B_ST_BYTES (BN * 128)
#define STAGE_BYTES (A_ST_BYTES + B_ST_BYTES)   // 49152
#define SMEM_TOTAL (NSTAGE * STAGE_BYTES)        // 147456

// Scratch (static device arrays: allocation-free contract)
__device__ __align__(16) __half  g_xh[(size_t)T_DIM * K_DIM];   // fp16(x)
__device__ __align__(16) __half  g_wh[(size_t)O_DIM * K_DIM];   // fp16(w*s)
__device__ __align__(16) uint8_t g_a8[(size_t)T_DIM * K8];      // e4m3 [xl8 | xh8]
__device__ __align__(16) uint8_t g_b8[(size_t)O_DIM * K8];      // e4m3 [wh8 | wl8]
__device__ float g_sxh[T_DIM];
__device__ float g_swh[O_DIM];

// ---------------------------------------------------------------- helpers
__device__ __forceinline__ uint32_t smem_u32(const void* p) {
    uint32_t a;
    asm("{ .reg .u64 t; cvta.to.shared.u64 t, %1; cvt.u32.u64 %0, t; }" : "=r"(a) : "l"(p));
    return a;
}
__device__ __forceinline__ uint32_t swz(uint32_t off) { return off ^ ((off >> 3) & 0x70); }

__device__ __forceinline__ void cp_async16(uint32_t dst, const void* src) {
    asm volatile("cp.async.cg.shared.global [%0], [%1], 16;\n" :: "r"(dst), "l"(src));
}
__device__ __forceinline__ void cp_commit() { asm volatile("cp.async.commit_group;\n" ::: "memory"); }
template <int N>
__device__ __forceinline__ void cp_wait() { asm volatile("cp.async.wait_group %0;\n" :: "n"(N) : "memory"); }

#define LDSM_X4(r, addr) \
    asm volatile("ldmatrix.sync.aligned.m8n8.x4.shared.b16 {%0,%1,%2,%3}, [%4];" \
        : "=r"((r)[0]), "=r"((r)[1]), "=r"((r)[2]), "=r"((r)[3]) : "r"(addr))

#define MMA16816(c, a, b0, b1) \
    asm volatile("mma.sync.aligned.m16n8k16.row.col.f32.f16.f16.f32 " \
        "{%0,%1,%2,%3}, {%4,%5,%6,%7}, {%8,%9}, {%0,%1,%2,%3};" \
        : "+f"((c)[0]), "+f"((c)[1]), "+f"((c)[2]), "+f"((c)[3]) \
        : "r"((a)[0]), "r"((a)[1]), "r"((a)[2]), "r"((a)[3]), "r"(b0), "r"(b1))

// FP8 e4m3 x e4m3 -> f32, byte-isomorphic fragment to the validated s8 k32 path
#define MMA16832F8(c, a, b0, b1) \
    asm volatile("mma.sync.aligned.m16n8k32.row.col.f32.e4m3.e4m3.f32 " \
        "{%0,%1,%2,%3}, {%4,%5,%6,%7}, {%8,%9}, {%0,%1,%2,%3};" \
        : "+f"((c)[0]), "+f"((c)[1]), "+f"((c)[2]), "+f"((c)[3]) \
        : "r"((a)[0]), "r"((a)[1]), "r"((a)[2]), "r"((a)[3]), "r"(b0), "r"(b1))

// pack 4 floats into 4 ascending e4m3 bytes (first cvt source -> HIGH byte)
__device__ __forceinline__ uint32_t pack4_e4m3(float f0, float f1, float f2, float f3) {
    uint16_t lo, hi;
    asm("cvt.rn.satfinite.e4m3x2.f32 %0, %1, %2;" : "=h"(lo) : "f"(f1), "f"(f0));
    asm("cvt.rn.satfinite.e4m3x2.f32 %0, %1, %2;" : "=h"(hi) : "f"(f3), "f"(f2));
    return (uint32_t)lo | ((uint32_t)hi << 16);
}

// ---------------------------------------------------------------- row-max kernels
__global__ void __launch_bounds__(256) rowmax_x(const float* __restrict__ x) {
    const int row = blockIdx.x;
    const float4* xr = reinterpret_cast<const float4*>(x + (size_t)row * K_DIM);
    float m = 0.f;
    for (int i = threadIdx.x; i < K_DIM / 4; i += 256) {
        float4 f = xr[i];
        m = fmaxf(m, fmaxf(fmaxf(fabsf(f.x), fabsf(f.y)), fmaxf(fabsf(f.z), fabsf(f.w))));
    }
    #pragma unroll
    for (int o = 16; o; o >>= 1) m = fmaxf(m, __shfl_xor_sync(~0u, m, o));
    __shared__ float sm[8];
    if ((threadIdx.x & 31) == 0) sm[threadIdx.x >> 5] = m;
    __syncthreads();
    if (threadIdx.x < 8) {
        float v = sm[threadIdx.x];
        #pragma unroll
        for (int o = 4; o; o >>= 1) v = fmaxf(v, __shfl_xor_sync(0xFFu, v, o));
        if (threadIdx.x == 0) g_sxh[row] = fmaxf(v, 1e-30f) * (1.f / 448.f);
    }
}

__global__ void __launch_bounds__(256) rowmax_w(const float* __restrict__ w,
                                                const float* __restrict__ s) {
    const int row = blockIdx.x;
    const float4* wr = reinterpret_cast<const float4*>(w + (size_t)row * K_DIM);
    const float* srow = s + (size_t)(row >> 6) * (K_DIM / QB);
    float m = 0.f;
    for (int i = threadIdx.x; i < K_DIM / 4; i += 256) {
        float sc = srow[(i * 4) >> 6];
        float4 f = wr[i];
        m = fmaxf(m, fmaxf(fmaxf(fabsf(f.x), fabsf(f.y)), fmaxf(fabsf(f.z), fabsf(f.w))) * sc);
    }
    #pragma unroll
    for (int o = 16; o; o >>= 1) m = fmaxf(m, __shfl_xor_sync(~0u, m, o));
    __shared__ float sm[8];
    if ((threadIdx.x & 31) == 0) sm[threadIdx.x >> 5] = m;
    __syncthreads();
    if (threadIdx.x < 8) {
        float v = sm[threadIdx.x];
        #pragma unroll
        for (int o = 4; o; o >>= 1) v = fmaxf(v, __shfl_xor_sync(0xFFu, v, o));
        if (threadIdx.x == 0) g_swh[row] = fmaxf(v, 1e-30f) * (1.f / 448.f);
    }
}

// ---------------------------------------------------------------- split/quant prep
__global__ void __launch_bounds__(256) xprep(const float* __restrict__ x) {
    const size_t n4 = (size_t)T_DIM * K_DIM / 4;
    for (size_t v = (size_t)blockIdx.x * blockDim.x + threadIdx.x; v < n4;
         v += (size_t)gridDim.x * blockDim.x) {
        size_t e = v * 4;
        size_t t = e >> 12;
        size_t i = e & 4095;
        const float inv = 1.f / g_sxh[t];
        float4 f = reinterpret_cast<const float4*>(x)[v];
        __half h0 = __float2half_rn(f.x), h1 = __float2half_rn(f.y);
        __half h2 = __float2half_rn(f.z), h3 = __float2half_rn(f.w);
        float l0 = f.x - __half2float(h0), l1 = f.y - __half2float(h1);
        float l2 = f.z - __half2float(h2), l3 = f.w - __half2float(h3);
        __half2 p0 = __halves2half2(h0, h1), p1 = __halves2half2(h2, h3);
        uint2 uh;
        uh.x = *reinterpret_cast<uint32_t*>(&p0);
        uh.y = *reinterpret_cast<uint32_t*>(&p1);
        *reinterpret_cast<uint2*>(g_xh + t * K_DIM + i) = uh;
        uint32_t ph = pack4_e4m3(f.x * inv, f.y * inv, f.z * inv, f.w * inv);
        const float invl = inv * 2048.f;
        uint32_t pl = pack4_e4m3(l0 * invl, l1 * invl, l2 * invl, l3 * invl);
        *reinterpret_cast<uint32_t*>(g_a8 + t * K8 + i) = pl;            // xl8
        *reinterpret_cast<uint32_t*>(g_a8 + t * K8 + K_DIM + i) = ph;    // xh8
    }
}

__global__ void __launch_bounds__(256) wprep(const float* __restrict__ w,
                                             const float* __restrict__ s) {
    const size_t n4 = (size_t)O_DIM * K_DIM / 4;
    for (size_t v = (size_t)blockIdx.x * blockDim.x + threadIdx.x; v < n4;
         v += (size_t)gridDim.x * blockDim.x) {
        size_t e = v * 4;
        size_t o = e >> 12;
        size_t i = e & 4095;
        float sc = s[(o >> 6) * (K_DIM / QB) + (i >> 6)];
        const float inv = 1.f / g_swh[o];
        float4 f = reinterpret_cast<const float4*>(w)[v];
        float d0 = f.x * sc, d1 = f.y * sc, d2 = f.z * sc, d3 = f.w * sc;
        __half h0 = __float2half_rn(d0), h1 = __float2half_rn(d1);
        __half h2 = __float2half_rn(d2), h3 = __float2half_rn(d3);
        float l0 = d0 - __half2float(h0), l1 = d1 - __half2float(h1);
        float l2 = d2 - __half2float(h2), l3 = d3 - __half2float(h3);
        __half2 p0 = __halves2half2(h0, h1), p1 = __halves2half2(h2, h3);
        uint2 uh;
        uh.x = *reinterpret_cast<uint32_t*>(&p0);
        uh.y = *reinterpret_cast<uint32_t*>(&p1);
        *reinterpret_cast<uint2*>(g_wh + o * K_DIM + i) = uh;
        uint32_t ph = pack4_e4m3(d0 * inv, d1 * inv, d2 * inv, d3 * inv);
        const float invl = inv * 2048.f;
        uint32_t pl = pack4_e4m3(l0 * invl, l1 * invl, l2 * invl, l3 * invl);
        *reinterpret_cast<uint32_t*>(g_b8 + o * K8 + i) = ph;            // wh8
        *reinterpret_cast<uint32_t*>(g_b8 + o * K8 + K_DIM + i) = pl;    // wl8
    }
}

// ---------------------------------------------------------------- fp8 correction GEMM
// out[r][c] = acc_f32 * sxh[r]*swh[c]/2048   (written first; fp16 GEMM accumulates)
__global__ void __launch_bounds__(NTHREADS, 1) gemm_f8(float* __restrict__ out) {
    extern __shared__ char smem[];
    const uint32_t sbase = smem_u32(smem);
    const int tid = threadIdx.x;
    const int wid = tid >> 5;
    const int lid = tid & 31;

    const int t0 = blockIdx.x * BM;
    const int o0 = blockIdx.y * BN;

    const uint8_t* Ag = g_a8 + (size_t)t0 * K8;
    const uint8_t* Bg = g_b8 + (size_t)o0 * K8;

    auto load_stage = [&](int st, int kb) {
        if (kb < KBLK8) {
            const uint32_t abase = sbase + st * STAGE_BYTES;
            const uint32_t bbase = abase + A_ST_BYTES;
            const int kk = kb * 128;
            #pragma unroll
            for (int c = tid; c < (BM + BN) * 8; c += NTHREADS) {
                int row = c >> 3, ch = c & 7;
                if (row < BM)
                    cp_async16(abase + swz(row * 128 + ch * 16),
                               Ag + (size_t)row * K8 + kk + ch * 16);
                else
                    cp_async16(bbase + swz((row - BM) * 128 + ch * 16),
                               Bg + (size_t)(row - BM) * K8 + kk + ch * 16);
            }
        }
        cp_commit();
    };

    const int warp_m = wid & 1;
    const int warp_n = wid >> 1;
    const int m_off = warp_m * 64;
    const int n_off = warp_n * 32;
    const int lrow = lid & 15;
    const int lc16 = lid >> 4;

    uint32_t preA[4], preB[2];
    #pragma unroll
    for (int mi = 0; mi < 4; mi++)
        preA[mi] = swz((uint32_t)((m_off + mi * 16 + lrow) * 128 + lc16 * 16));
    #pragma unroll
    for (int nj = 0; nj < 2; nj++)
        preB[nj] = swz((uint32_t)((n_off + nj * 16 + lrow) * 128 + lc16 * 16));

    float acc[4][4][4];
    #pragma unroll
    for (int mi = 0; mi < 4; mi++)
        #pragma unroll
        for (int ni = 0; ni < 4; ni++)
            #pragma unroll
            for (int q = 0; q < 4; q++) acc[mi][ni][q] = 0.f;

    load_stage(0, 0);
    load_stage(1, 1);

    for (int kb = 0; kb < KBLK8; kb++) {
        cp_wait<1>();
        __syncthreads();
        load_stage((kb + 2) % NSTAGE, kb + 2);

        const uint32_t sA = sbase + (kb % NSTAGE) * STAGE_BYTES;
        const uint32_t sB = sA + A_ST_BYTES;
        #pragma unroll
        for (int ks = 0; ks < 4; ks++) {   // 4 x k32 (32B) steps per 128B slab
            const uint32_t xk = ks * 32;
            uint32_t a[4][4], b[2][4];
            #pragma unroll
            for (int mi = 0; mi < 4; mi++) LDSM_X4(a[mi], sA + (preA[mi] ^ xk));
            #pragma unroll
            for (int nj = 0; nj < 2; nj++) LDSM_X4(b[nj], sB + (preB[nj] ^ xk));
            #pragma unroll
            for (int mi = 0; mi < 4; mi++)
                #pragma unroll
                for (int ni = 0; ni < 4; ni++)
                    MMA16832F8(acc[mi][ni], a[mi], b[ni >> 1][ni & 1], b[ni >> 1][2 + (ni & 1)]);
        }
    }

    // Epilogue: scale and write
    #pragma unroll
    for (int mi = 0; mi < 4; mi++) {
        const int r0 = t0 + m_off + mi * 16 + (lid >> 2);
        const float sr0 = g_sxh[r0] * (1.f / 2048.f);
        const float sr1 = g_sxh[r0 + 8] * (1.f / 2048.f);
        #pragma unroll
        for (int ni = 0; ni < 4; ni++) {
            const int c = o0 + n_off + ni * 8 + ((lid & 3) << 1);
            const float sc0 = g_swh[c], sc1 = g_swh[c + 1];
            *reinterpret_cast<float2*>(out + (size_t)r0 * O_DIM + c) =
                make_float2(acc[mi][ni][0] * sr0 * sc0, acc[mi][ni][1] * sr0 * sc1);
            *reinterpret_cast<float2*>(out + (size_t)(r0 + 8) * O_DIM + c) =
                make_float2(acc[mi][ni][2] * sr1 * sc0, acc[mi][ni][3] * sr1 * sc1);
        }
    }
}

// ---------------------------------------------------------------- fp16 main GEMM (accumulates)
__global__ void __launch_bounds__(NTHREADS, 1) gemm_f16(float* __restrict__ out) {
    extern __shared__ char smem[];
    const uint32_t sbase = smem_u32(smem);
    const int tid = threadIdx.x;
    const int wid = tid >> 5;
    const int lid = tid & 31;

    const int t0 = blockIdx.x * BM;
    const int o0 = blockIdx.y * BN;

    const __half* Ag = g_xh + (size_t)t0 * K_DIM;
    const __half* Bg = g_wh + (size_t)o0 * K_DIM;

    auto load_stage = [&](int st, int kb) {
        if (kb < KBLK16) {
            const uint32_t abase = sbase + st * STAGE_BYTES;
            const uint32_t bbase = abase + A_ST_BYTES;
            const int kk = kb * 64;
            #pragma unroll
            for (int c = tid; c < (BM + BN) * 8; c += NTHREADS) {
                int row = c >> 3, ch = c & 7;
                if (row < BM)
                    cp_async16(abase + swz(row * 128 + ch * 16),
                               Ag + (size_t)row * K_DIM + kk + ch * 8);
                else
                    cp_async16(bbase + swz((row - BM) * 128 + ch * 16),
                               Bg + (size_t)(row - BM) * K_DIM + kk + ch * 8);
            }
        }
        cp_commit();
    };

    const int warp_m = wid & 1;
    const int warp_n = wid >> 1;
    const int m_off = warp_m * 64;
    const int n_off = warp_n * 32;
    const int lrow = lid & 15;
    const int lc16 = lid >> 4;

    uint32_t preA[4], preB[2];
    #pragma unroll
    for (int mi = 0; mi < 4; mi++)
        preA[mi] = swz((uint32_t)((m_off + mi * 16 + lrow) * 128 + lc16 * 16));
    #pragma unroll
    for (int nj = 0; nj < 2; nj++)
        preB[nj] = swz((uint32_t)((n_off + nj * 16 + lrow) * 128 + lc16 * 16));

    float acc[4][4][4];
    #pragma unroll
    for (int mi = 0; mi < 4; mi++)
        #pragma unroll
        for (int ni = 0; ni < 4; ni++)
            #pragma unroll
            for (int q = 0; q < 4; q++) acc[mi][ni][q] = 0.f;

    load_stage(0, 0);
    load_stage(1, 1);

    for (int kb = 0; kb < KBLK16; kb++) {
        cp_wait<1>();
        __syncthreads();
        load_stage((kb + 2) % NSTAGE, kb + 2);

        const uint32_t sA = sbase + (kb % NSTAGE) * STAGE_BYTES;
        const uint32_t sB = sA + A_ST_BYTES;
        #pragma unroll
        for (int ks = 0; ks < 4; ks++) {
            const uint32_t xk = ks * 32;
            uint32_t a[4][4], b[2][4];
            #pragma unroll
            for (int mi = 0; mi < 4; mi++) LDSM_X4(a[mi], sA + (preA[mi] ^ xk));
            #pragma unroll
            for (int nj = 0; nj < 2; nj++) LDSM_X4(b[nj], sB + (preB[nj] ^ xk));
            #pragma unroll
            for (int mi = 0; mi < 4; mi++)
                #pragma unroll
                for (int ni = 0; ni < 4; ni++)
                    MMA16816(acc[mi][ni], a[mi], b[ni >> 1][ni & 1], b[ni >> 1][2 + (ni & 1)]);
        }
    }

    // Epilogue: accumulate onto fp8-correction result
    #pragma unroll
    for (int mi = 0; mi < 4; mi++) {
        const int r0 = t0 + m_off + mi * 16 + (lid >> 2);
        #pragma unroll
        for (int ni = 0; ni < 4; ni++) {
            const int c = o0 + n_off + ni * 8 + ((lid & 3) << 1);
            float2* p0 = reinterpret_cast<float2*>(out + (size_t)r0 * O_DIM + c);
            float2* p1 = reinterpret_cast<float2*>(out + (size_t)(r0 + 8) * O_DIM + c);
            float2 v0 = *p0, v1 = *p1;
            v0.x += acc[mi][ni][0]; v0.y += acc[mi][ni][1];
            v1.x += acc[mi][ni][2]; v1.y += acc[mi][ni][3];
            *p0 = v0; *p1 = v1;
        }
    }
}

// ---------------------------------------------------------------- launch
extern "C" void kernel_launch(void* const* d_in, const int* in_sizes, int n_in,
                              void* d_out, int out_size) {
    (void)in_sizes; (void)n_in; (void)out_size;
    const float* x = (const float*)d_in[0];
    const float* w = (const float*)d_in[1];
    const float* s = (const float*)d_in[2];
    float* out = (float*)d_out;

    rowmax_x<<<T_DIM, 256>>>(x);
    rowmax_w<<<O_DIM, 256>>>(w, s);
    xprep<<<2048, 256>>>(x);
    wprep<<<2048, 256>>>(w, s);

    cudaFuncSetAttribute(gemm_f8, cudaFuncAttributeMaxDynamicSharedMemorySize, SMEM_TOTAL);
    cudaFuncSetAttribute(gemm_f16, cudaFuncAttributeMaxDynamicSharedMemorySize, SMEM_TOTAL);
    dim3 grid(T_DIM / BM, O_DIM / BN);  // (64, 43)
    gemm_f8<<<grid, NTHREADS, SMEM_TOTAL>>>(out);   // writes out = correction
    gemm_f16<<<grid, NTHREADS, SMEM_TOTAL>>>(out);  // out += main product
}

// round 6
// speedup vs baseline: 2.2988x; 1.2150x over previous
#include <cuda_runtime.h>
#include <cuda_fp16.h>
#include <cstdint>

// Problem dims
#define T_DIM 8192
#define K_DIM 4096
#define O_DIM 11008
#define QB    64

// Two-term split: A row = [xh(4096) | xl(4096)], B row = [wh(4096) | wl(4096)]
#define AK 8192

// GEMM tiling
#define BM 128
#define BN 256
#define BK 64                       // 64 fp16 = 128 B per row = one SW128 atom row
#define NSTAGE 4
#define KBLKS 192                   // 64 (xh*wh) + 64 (xh*wl) + 64 (xl*wh)
#define NTHREADS 512

#define A_ST_BYTES (BM * 128)       // 16384
#define B_ST_BYTES (BN * 128)       // 32768
#define STAGE_BYTES (A_ST_BYTES + B_ST_BYTES)  // 49152
#define SMEM_TOTAL (NSTAGE * STAGE_BYTES)       // 196608

// fp16 scratch (static device arrays: allocation-free contract)
__device__ __align__(16) __half g_a[(size_t)T_DIM * AK];   // [xh | xl]
__device__ __align__(16) __half g_b[(size_t)O_DIM * AK];   // [wh | wl]

// ---------------------------------------------------------------- helpers
__device__ __forceinline__ uint32_t smem_u32(const void* p) {
    uint32_t a;
    asm("{ .reg .u64 t; cvta.to.shared.u64 t, %1; cvt.u32.u64 %0, t; }" : "=r"(a) : "l"(p));
    return a;
}
__device__ __forceinline__ uint32_t swz(uint32_t off) { return off ^ ((off >> 3) & 0x70); }

__device__ __forceinline__ void cp_async16(uint32_t dst, const void* src) {
    asm volatile("cp.async.cg.shared.global [%0], [%1], 16;\n" :: "r"(dst), "l"(src));
}
__device__ __forceinline__ void cp_commit() { asm volatile("cp.async.commit_group;\n" ::: "memory"); }
template <int N>
__device__ __forceinline__ void cp_wait() { asm volatile("cp.async.wait_group %0;\n" :: "n"(N) : "memory"); }

#define LDSM_X4(r, addr) \
    asm volatile("ldmatrix.sync.aligned.m8n8.x4.shared.b16 {%0,%1,%2,%3}, [%4];" \
        : "=r"((r)[0]), "=r"((r)[1]), "=r"((r)[2]), "=r"((r)[3]) : "r"(addr))

#define MMA16816(c, a, b0, b1) \
    asm volatile("mma.sync.aligned.m16n8k16.row.col.f32.f16.f16.f32 " \
        "{%0,%1,%2,%3}, {%4,%5,%6,%7}, {%8,%9}, {%0,%1,%2,%3};" \
        : "+f"((c)[0]), "+f"((c)[1]), "+f"((c)[2]), "+f"((c)[3]) \
        : "r"((a)[0]), "r"((a)[1]), "r"((a)[2]), "r"((a)[3]), "r"(b0), "r"(b1))

// ---------------------------------------------------------------- prep kernels
// Split x into hi/lo fp16 halves: g_a row t = [fp16(x), fp16(x - fp16(x))]
__global__ void __launch_bounds__(256) xsplit_kernel(const float* __restrict__ x) {
    const size_t n4 = (size_t)T_DIM * K_DIM / 4;
    for (size_t v = (size_t)blockIdx.x * blockDim.x + threadIdx.x; v < n4;
         v += (size_t)gridDim.x * blockDim.x) {
        size_t e = v * 4;
        size_t t = e >> 12;
        size_t i = e & 4095;
        float4 f = reinterpret_cast<const float4*>(x)[v];
        __half h0 = __float2half_rn(f.x), h1 = __float2half_rn(f.y);
        __half h2 = __float2half_rn(f.z), h3 = __float2half_rn(f.w);
        __half l0 = __float2half_rn(f.x - __half2float(h0));
        __half l1 = __float2half_rn(f.y - __half2float(h1));
        __half l2 = __float2half_rn(f.z - __half2float(h2));
        __half l3 = __float2half_rn(f.w - __half2float(h3));
        __half2 hi0 = __halves2half2(h0, h1), hi1 = __halves2half2(h2, h3);
        __half2 lo0 = __halves2half2(l0, l1), lo1 = __halves2half2(l2, l3);
        uint2 uh, ul;
        uh.x = *reinterpret_cast<uint32_t*>(&hi0); uh.y = *reinterpret_cast<uint32_t*>(&hi1);
        ul.x = *reinterpret_cast<uint32_t*>(&lo0); ul.y = *reinterpret_cast<uint32_t*>(&lo1);
        *reinterpret_cast<uint2*>(g_a + t * AK + i) = uh;
        *reinterpret_cast<uint2*>(g_a + t * AK + K_DIM + i) = ul;
    }
}

// Dequant + split weight: g_b row o = [fp16(w*s), fp16(w*s - fp16(w*s))]
__global__ void __launch_bounds__(256) wsplit_kernel(const float* __restrict__ w,
                                                     const float* __restrict__ s) {
    const size_t n4 = (size_t)O_DIM * K_DIM / 4;
    const int SCOLS = K_DIM / QB;  // 64
    for (size_t v = (size_t)blockIdx.x * blockDim.x + threadIdx.x; v < n4;
         v += (size_t)gridDim.x * blockDim.x) {
        size_t e = v * 4;
        size_t o = e >> 12;
        size_t i = e & 4095;
        float sc = s[(o >> 6) * SCOLS + (i >> 6)];
        float4 f = reinterpret_cast<const float4*>(w)[v];
        float d0 = f.x * sc, d1 = f.y * sc, d2 = f.z * sc, d3 = f.w * sc;
        __half h0 = __float2half_rn(d0), h1 = __float2half_rn(d1);
        __half h2 = __float2half_rn(d2), h3 = __float2half_rn(d3);
        __half l0 = __float2half_rn(d0 - __half2float(h0));
        __half l1 = __float2half_rn(d1 - __half2float(h1));
        __half l2 = __float2half_rn(d2 - __half2float(h2));
        __half l3 = __float2half_rn(d3 - __half2float(h3));
        __half2 hi0 = __halves2half2(h0, h1), hi1 = __halves2half2(h2, h3);
        __half2 lo0 = __halves2half2(l0, l1), lo1 = __halves2half2(l2, l3);
        uint2 uh, ul;
        uh.x = *reinterpret_cast<uint32_t*>(&hi0); uh.y = *reinterpret_cast<uint32_t*>(&hi1);
        ul.x = *reinterpret_cast<uint32_t*>(&lo0); ul.y = *reinterpret_cast<uint32_t*>(&lo1);
        *reinterpret_cast<uint2*>(g_b + o * AK + i) = uh;
        *reinterpret_cast<uint2*>(g_b + o * AK + K_DIM + i) = ul;
    }
}

// Per-stage K-block remap for the 3-product schedule:
//   kb in [0,64):    xh (A col kb)      * wh (B col kb)
//   kb in [64,128):  xh (A col kb-64)   * wl (B col kb)       [wl lives at +4096]
//   kb in [128,192): xl (A col kb-64)   * wh (B col kb-128)   [xl lives at +4096]
__device__ __forceinline__ int a_kblk(int kb) { return (kb < 128) ? (kb & 63) : (kb - 64); }
__device__ __forceinline__ int b_kblk(int kb) { return (kb < 128) ? kb : (kb - 128); }

// ---------------------------------------------------------------- GEMM
__global__ void __launch_bounds__(NTHREADS, 1) gemm_kernel(float* __restrict__ out) {
    extern __shared__ char smem[];
    const uint32_t sbase = smem_u32(smem);
    const int tid = threadIdx.x;
    const int wid = tid >> 5;
    const int lid = tid & 31;

    const int t0 = blockIdx.x * BM;   // m fastest-varying for B-tile L2 reuse
    const int o0 = blockIdx.y * BN;

    const __half* Ag = g_a + (size_t)t0 * AK;
    const __half* Bg = g_b + (size_t)o0 * AK;

    auto load_stage = [&](int st, int kb) {
        if (kb < KBLKS) {
            const uint32_t abase = sbase + st * STAGE_BYTES;
            const uint32_t bbase = abase + A_ST_BYTES;
            const int ak = a_kblk(kb) * BK;
            const int bk = b_kblk(kb) * BK;
            #pragma unroll
            for (int c = tid; c < (BM + BN) * 8; c += NTHREADS) {
                int row = c >> 3, ch = c & 7;
                if (row < BM)
                    cp_async16(abase + swz(row * 128 + ch * 16),
                               Ag + (size_t)row * AK + ak + ch * 8);
                else
                    cp_async16(bbase + swz((row - BM) * 128 + ch * 16),
                               Bg + (size_t)(row - BM) * AK + bk + ch * 8);
            }
        }
        cp_commit();
    };

    // 16 warps in 2(m) x 8(n) grid; warp tile 64x32; mma.m16n8k16 f16->f32.
    const int warp_m = wid & 1;
    const int warp_n = wid >> 1;
    const int m_off = warp_m * 64;
    const int n_off = warp_n * 32;
    const int lrow = lid & 15;
    const int lc16 = lid >> 4;

    uint32_t preA[4], preB[2];
    #pragma unroll
    for (int mi = 0; mi < 4; mi++)
        preA[mi] = swz((uint32_t)((m_off + mi * 16 + lrow) * 128 + lc16 * 16));
    #pragma unroll
    for (int nj = 0; nj < 2; nj++)
        preB[nj] = swz((uint32_t)((n_off + nj * 16 + lrow) * 128 + lc16 * 16));

    float acc[4][4][4];
    #pragma unroll
    for (int mi = 0; mi < 4; mi++)
        #pragma unroll
        for (int ni = 0; ni < 4; ni++)
            #pragma unroll
            for (int q = 0; q < 4; q++) acc[mi][ni][q] = 0.f;

    // prologue: 3 stages in flight
    load_stage(0, 0);
    load_stage(1, 1);
    load_stage(2, 2);

    for (int kb = 0; kb < KBLKS; kb++) {
        cp_wait<2>();          // group kb complete; kb+1, kb+2 still in flight
        __syncthreads();
        load_stage((kb + 3) & (NSTAGE - 1), kb + 3);   // issue before compute

        const uint32_t sA = sbase + (kb & (NSTAGE - 1)) * STAGE_BYTES;
        const uint32_t sB = sA + A_ST_BYTES;
        #pragma unroll
        for (int ks = 0; ks < 4; ks++) {
            const uint32_t xk = ks * 32;
            uint32_t a[4][4], b[2][4];
            #pragma unroll
            for (int mi = 0; mi < 4; mi++) LDSM_X4(a[mi], sA + (preA[mi] ^ xk));
            #pragma unroll
            for (int nj = 0; nj < 2; nj++) LDSM_X4(b[nj], sB + (preB[nj] ^ xk));
            #pragma unroll
            for (int mi = 0; mi < 4; mi++)
                #pragma unroll
                for (int ni = 0; ni < 4; ni++)
                    MMA16816(acc[mi][ni], a[mi], b[ni >> 1][ni & 1], b[ni >> 1][2 + (ni & 1)]);
        }
    }

    // Epilogue: direct register -> gmem float2 stores
    #pragma unroll
    for (int mi = 0; mi < 4; mi++) {
        const int r0 = t0 + m_off + mi * 16 + (lid >> 2);
        #pragma unroll
        for (int ni = 0; ni < 4; ni++) {
            const int c = o0 + n_off + ni * 8 + ((lid & 3) << 1);
            *reinterpret_cast<float2*>(out + (size_t)r0 * O_DIM + c) =
                make_float2(acc[mi][ni][0], acc[mi][ni][1]);
            *reinterpret_cast<float2*>(out + (size_t)(r0 + 8) * O_DIM + c) =
                make_float2(acc[mi][ni][2], acc[mi][ni][3]);
        }
    }
}

// ---------------------------------------------------------------- launch
extern "C" void kernel_launch(void* const* d_in, const int* in_sizes, int n_in,
                              void* d_out, int out_size) {
    (void)in_sizes; (void)n_in; (void)out_size;
    const float* x = (const float*)d_in[0];
    const float* w = (const float*)d_in[1];
    const float* s = (const float*)d_in[2];
    float* out = (float*)d_out;

    xsplit_kernel<<<2048, 256>>>(x);
    wsplit_kernel<<<2048, 256>>>(w, s);

    cudaFuncSetAttribute(gemm_kernel, cudaFuncAttributeMaxDynamicSharedMemorySize, SMEM_TOTAL);
    dim3 grid(T_DIM / BM, O_DIM / BN);  // (64, 43), m fastest
    gemm_kernel<<<grid, NTHREADS, SMEM_TOTAL>>>(out);
}